// round 8
// baseline (speedup 1.0000x reference)
#include <cuda_runtime.h>
#include <cstdint>

#define CAND 512           // candidate buffer entries (u64)
#define TBL  2048          // bins per table
#define XSCALE 102.4f      // TBL / 20  (range [-10, 10])
#define XOFF   1024.0f     // 10 * XSCALE
#define THRESH0 2.7f       // prefilter threshold (fallback makes any value correct)
#define FULLM 0xFFFFFFFFu

static __device__ float g_rowsum[8192];
static __device__ float g_table[2 * TBL];          // [0..TBL)=f_neg, [TBL..2TBL)=f_pos
static __device__ unsigned char g_catbit[16384];   // (1<<(cat-1))&7
static __device__ int   g_count = 0;

// ---------------------------------------------------------------------------
__device__ __forceinline__ unsigned sortkey32(float x) {
    unsigned u = __float_as_uint(x);
    return u ^ ((unsigned)(((int)u) >> 31) | 0x80000000u);
}
__device__ __forceinline__ unsigned long long makekey(unsigned k32, int c) {
    return ((unsigned long long)k32 << 32) |
           (unsigned long long)(0xFFFFFFFFu - (unsigned)c);
}
__device__ __forceinline__ int tbl_idx(float xv) {
    float fx = fmaf(xv, XSCALE, XOFF);
    fx = fminf(fx, 2047.0f);
    fx = fmaxf(fx, 0.0f);
    return (int)fx;
}

// ---------------------------------------------------------------------------
// Kernel 0: build loss tables (exact math) + catbit LUT.
// ---------------------------------------------------------------------------
__global__ void asl_build(const int* __restrict__ cat, int C)
{
    int j = blockIdx.x * 256 + threadIdx.x;
    if (j < 2 * TBL) {
        bool pos = j >= TBL;
        int  q   = pos ? j - TBL : j;
        float x  = (q + 0.5f) * (20.0f / TBL) - 10.0f;
        float sp = 1.0f / (1.0f + expf(-x));
        float v;
        if (pos) {
            v = logf(fmaxf(sp, 1e-8f)) * (1.0f - sp);
        } else {
            float pv = fminf(1.05f - sp, 1.0f);
            float om = 1.0f - pv;
            float om2 = om * om;
            v = logf(fmaxf(pv, 1e-8f)) * om2 * om2;
        }
        g_table[j] = v;
    }
    int c = j - 2 * TBL;
    if (c >= 0 && c < C)
        g_catbit[c] = (unsigned char)((1 << (cat[c] - 1)) & 7);
}

// ---------------------------------------------------------------------------
// Kernel 1: one block per row.
// ---------------------------------------------------------------------------
__global__ void __launch_bounds__(256, 6)
asl_row_kernel(const float* __restrict__ X,
               const float* __restrict__ Y,
               const int*   __restrict__ cat,
               const unsigned char* __restrict__ inmap,
               int C, int B, float* __restrict__ out)
{
    const int row  = blockIdx.x;
    const int tid  = threadIdx.x;
    const int lane = tid & 31;
    const int warp = tid >> 5;

    const float* __restrict__ xr = X + (size_t)row * C;
    const float* __restrict__ yr = Y + (size_t)row * C;

    __shared__ float s_tbl[2 * TBL];              // 16 KB
    __shared__ unsigned long long s_buf[CAND];    // 4 KB
    __shared__ unsigned long long s_top[10];
    __shared__ float s_sumw[8];
    __shared__ int s_flags, s_cnt, s_last;

    {   // table L2 -> smem
        const float4* gt = (const float4*)g_table;
        float4* st = (float4*)s_tbl;
#pragma unroll
        for (int i = tid; i < (2 * TBL) / 4; i += 256) st[i] = gt[i];
    }
    if (tid == 0) { s_flags = 0; s_cnt = 0; }
    __syncthreads();

    float sum = 0.0f;
    int flags = 0;

    // alignment: first element index whose address is 16B aligned
    const int p = (int)((4 - (((size_t)row * (size_t)C) & 3)) & 3);
    const int nv = (C - p) >> 2;
    const int t0 = p + (nv << 2);

    // prologue + tail (<=3 elements each)
    for (int c = tid; c < p; c += 256) {
        const float xv = xr[c], yv = yr[c];
        const int j = tbl_idx(xv);
        sum += s_tbl[j];
        if (yv != 0.0f) { sum += s_tbl[j + TBL] - s_tbl[j]; flags |= g_catbit[c]; }
        if (xv > THRESH0) {
            int q = atomicAdd(&s_cnt, 1);
            if (q < CAND) s_buf[q] = makekey(sortkey32(xv), c);
        }
    }
    for (int c = t0 + tid; c < C; c += 256) {
        const float xv = xr[c], yv = yr[c];
        const int j = tbl_idx(xv);
        sum += s_tbl[j];
        if (yv != 0.0f) { sum += s_tbl[j + TBL] - s_tbl[j]; flags |= g_catbit[c]; }
        if (xv > THRESH0) {
            int q = atomicAdd(&s_cnt, 1);
            if (q < CAND) s_buf[q] = makekey(sortkey32(xv), c);
        }
    }

    // ---- main streaming loop: 2 quads (8 elements) per iteration ----
    const float4* __restrict__ x4 = (const float4*)(xr + p);
    const float4* __restrict__ y4 = (const float4*)(yr + p);

    for (int v0 = tid; v0 < nv; v0 += 512) {
        const int v1 = v0 + 256;
        const bool hb = (v1 < nv);

        const float4 xa = x4[v0];
        const float4 ya = y4[v0];
        float4 xb, yb;
        if (hb) { xb = x4[v1]; yb = y4[v1]; }
        else    { xb = make_float4(0.f, 0.f, 0.f, 0.f); yb = xb; }

        // unconditional neg-table sums
        sum += s_tbl[tbl_idx(xa.x)];
        sum += s_tbl[tbl_idx(xa.y)];
        sum += s_tbl[tbl_idx(xa.z)];
        sum += s_tbl[tbl_idx(xa.w)];
        if (hb) {
            sum += s_tbl[tbl_idx(xb.x)];
            sum += s_tbl[tbl_idx(xb.y)];
            sum += s_tbl[tbl_idx(xb.z)];
            sum += s_tbl[tbl_idx(xb.w)];
        }

        // 8-wide candidate gate
        const float xm = fmaxf(fmaxf(fmaxf(xa.x, xa.y), fmaxf(xa.z, xa.w)),
                               fmaxf(fmaxf(xb.x, xb.y), fmaxf(xb.z, xb.w)));
        if (xm > THRESH0) {
            const int ca = p + (v0 << 2);
            if (xa.x > THRESH0) { int q = atomicAdd(&s_cnt, 1); if (q < CAND) s_buf[q] = makekey(sortkey32(xa.x), ca + 0); }
            if (xa.y > THRESH0) { int q = atomicAdd(&s_cnt, 1); if (q < CAND) s_buf[q] = makekey(sortkey32(xa.y), ca + 1); }
            if (xa.z > THRESH0) { int q = atomicAdd(&s_cnt, 1); if (q < CAND) s_buf[q] = makekey(sortkey32(xa.z), ca + 2); }
            if (xa.w > THRESH0) { int q = atomicAdd(&s_cnt, 1); if (q < CAND) s_buf[q] = makekey(sortkey32(xa.w), ca + 3); }
            if (hb) {
                const int cb = p + (v1 << 2);
                if (xb.x > THRESH0) { int q = atomicAdd(&s_cnt, 1); if (q < CAND) s_buf[q] = makekey(sortkey32(xb.x), cb + 0); }
                if (xb.y > THRESH0) { int q = atomicAdd(&s_cnt, 1); if (q < CAND) s_buf[q] = makekey(sortkey32(xb.y), cb + 1); }
                if (xb.z > THRESH0) { int q = atomicAdd(&s_cnt, 1); if (q < CAND) s_buf[q] = makekey(sortkey32(xb.z), cb + 2); }
                if (xb.w > THRESH0) { int q = atomicAdd(&s_cnt, 1); if (q < CAND) s_buf[q] = makekey(sortkey32(xb.w), cb + 3); }
            }
        }

        // 8-wide positive gate (y is exactly 0 or 1)
        const float ym = fmaxf(fmaxf(fmaxf(ya.x, ya.y), fmaxf(ya.z, ya.w)),
                               fmaxf(fmaxf(yb.x, yb.y), fmaxf(yb.z, yb.w)));
        if (ym != 0.0f) {
            const int ca = p + (v0 << 2);
            if (ya.x != 0.0f) { int j = tbl_idx(xa.x); sum += s_tbl[j + TBL] - s_tbl[j]; flags |= g_catbit[ca + 0]; }
            if (ya.y != 0.0f) { int j = tbl_idx(xa.y); sum += s_tbl[j + TBL] - s_tbl[j]; flags |= g_catbit[ca + 1]; }
            if (ya.z != 0.0f) { int j = tbl_idx(xa.z); sum += s_tbl[j + TBL] - s_tbl[j]; flags |= g_catbit[ca + 2]; }
            if (ya.w != 0.0f) { int j = tbl_idx(xa.w); sum += s_tbl[j + TBL] - s_tbl[j]; flags |= g_catbit[ca + 3]; }
            if (hb) {
                const int cb = p + (v1 << 2);
                if (yb.x != 0.0f) { int j = tbl_idx(xb.x); sum += s_tbl[j + TBL] - s_tbl[j]; flags |= g_catbit[cb + 0]; }
                if (yb.y != 0.0f) { int j = tbl_idx(xb.y); sum += s_tbl[j + TBL] - s_tbl[j]; flags |= g_catbit[cb + 1]; }
                if (yb.z != 0.0f) { int j = tbl_idx(xb.z); sum += s_tbl[j + TBL] - s_tbl[j]; flags |= g_catbit[cb + 2]; }
                if (yb.w != 0.0f) { int j = tbl_idx(xb.w); sum += s_tbl[j + TBL] - s_tbl[j]; flags |= g_catbit[cb + 3]; }
            }
        }
    }

    // ---- reduce sum & flags ----
#pragma unroll
    for (int off = 16; off; off >>= 1) {
        sum   += __shfl_down_sync(FULLM, sum, off);
        flags |= __shfl_down_sync(FULLM, flags, off);
    }
    if (lane == 0) { s_sumw[warp] = sum; atomicOr(&s_flags, flags); }
    __syncthreads();

    // ---- resolve exact top-10 (fast path: 10 <= n <= CAND on first try) ----
    float thF = THRESH0;
    unsigned long long thK = 0ULL;
    bool useKey = false;
    int iter = 0;
    for (;;) {
        const int n = s_cnt;
        if ((n >= 10 && n <= CAND) || iter >= 32) {
            if (warp == 0) {
                const int m = min(n, CAND);
                for (int k = 0; k < 10; ++k) {
                    unsigned long long v = 0ULL;
                    for (int i = lane; i < m; i += 32) {
                        unsigned long long b = s_buf[i];
                        if (b > v) v = b;
                    }
#pragma unroll
                    for (int off = 16; off; off >>= 1) {
                        unsigned long long o = __shfl_down_sync(FULLM, v, off);
                        if (o > v) v = o;
                    }
                    unsigned long long w = __shfl_sync(FULLM, v, 0);
                    if (lane == 0) s_top[k] = w;
                    for (int i = lane; i < m; i += 32)
                        if (s_buf[i] == w) s_buf[i] = 0ULL;
                }
            }
            __syncthreads();
            break;
        }
        if (n > CAND) {
            // raise threshold to the 10th-largest key among stored candidates
            if (warp == 0) {
                for (int k = 0; k < 10; ++k) {
                    unsigned long long v = 0ULL;
                    for (int i = lane; i < CAND; i += 32) {
                        unsigned long long b = s_buf[i];
                        if (b > v) v = b;
                    }
#pragma unroll
                    for (int off = 16; off; off >>= 1) {
                        unsigned long long o = __shfl_down_sync(FULLM, v, off);
                        if (o > v) v = o;
                    }
                    unsigned long long w = __shfl_sync(FULLM, v, 0);
                    if (lane == 0) s_top[k] = w;
                    for (int i = lane; i < CAND; i += 32)
                        if (s_buf[i] == w) s_buf[i] = 0ULL;
                }
            }
            __syncthreads();
            thK = s_top[9];
            useKey = true;       // recollect with key >= thK (>=10 guaranteed)
        } else {
            thF -= 4.0f;         // too few: lower the float threshold
            useKey = false;
        }
        __syncthreads();
        if (tid == 0) s_cnt = 0;
        __syncthreads();
        for (int c = tid; c < C; c += 256) {
            const float xv = xr[c];
            if (useKey) {
                unsigned long long key = makekey(sortkey32(xv), c);
                if (key >= thK) {
                    int q = atomicAdd(&s_cnt, 1);
                    if (q < CAND) s_buf[q] = key;
                }
            } else if (xv > thF) {
                int q = atomicAdd(&s_cnt, 1);
                if (q < CAND) s_buf[q] = makekey(sortkey32(xv), c);
            }
        }
        __syncthreads();
        ++iter;
    }

    // ---- correction for the top-10 elements (exact math) ----
    const int fl = s_flags;
    const bool p1 = (fl & 1) != 0, p2 = (fl & 2) != 0, p3 = (fl & 4) != 0;
    const bool has4 = !(p1 | p2 | p3);

    float delta = 0.0f;
    if (tid < 10 && s_top[tid] != 0ULL) {
        const unsigned idx = 0xFFFFFFFFu - (unsigned)(s_top[tid] & 0xFFFFFFFFull);
        const float xv = xr[idx];
        const float yv = yr[idx];
        const float sp = __fdividef(1.0f, 1.0f + __expf(-xv));
        const float sn = fminf(1.05f - sp, 1.0f);
        const bool  pos = (yv != 0.0f);
        const float pv  = pos ? sp : sn;
        const float l   = __logf(fmaxf(pv, 1e-8f));
        const float om  = 1.0f - pv;
        const float om2 = om * om;
        const float w   = pos ? om : om2 * om2;

        const int  cv  = cat[idx];
        const bool inm = inmap[idx] != 0;
        const bool condA = (!inm) && has4;
        const bool condB = (cv == 1 && p1) || (cv == 2 && p2) ||
                           (cv == 3 && p3) || (cv == 4 && has4);
        if (condA || condB) {
            const float factor = (pos ? sn : sp) * 2.0f;   // ALPHA3 = 2
            delta = l * w * (factor - 1.0f);
        }
    }
    if (warp == 0) {
#pragma unroll
        for (int off = 16; off; off >>= 1)
            delta += __shfl_down_sync(FULLM, delta, off);
    }
    if (tid == 0) {
        float tot = delta;
#pragma unroll
        for (int i = 0; i < 8; ++i) tot += s_sumw[i];
        g_rowsum[row] = tot;
    }

    // ---- last-block finalize: deterministic double reduction ----
    __threadfence();
    if (tid == 0) s_last = (atomicAdd(&g_count, 1) == gridDim.x - 1) ? 1 : 0;
    __syncthreads();
    if (s_last) {
        __threadfence();
        double* sd = (double*)s_buf;
        double acc = 0.0;
        for (int i = tid; i < B; i += 256) acc += (double)g_rowsum[i];
        sd[tid] = acc;
        __syncthreads();
#pragma unroll
        for (int off = 128; off; off >>= 1) {
            if (tid < off) sd[tid] += sd[tid + off];
            __syncthreads();
        }
        if (tid == 0) { out[0] = -(float)sd[0]; g_count = 0; }
    }
}

extern "C" void kernel_launch(void* const* d_in, const int* in_sizes, int n_in,
                              void* d_out, int out_size)
{
    const float*         X   = (const float*)d_in[0];
    const float*         Y   = (const float*)d_in[1];
    const int*           cat = (const int*)d_in[2];
    const unsigned char* inm = (const unsigned char*)d_in[3];

    const int C = in_sizes[2];        // per-class arrays -> 9605
    const int B = in_sizes[0] / C;    // 2048

    asl_build<<<(2 * TBL + C + 255) / 256, 256>>>(cat, C);
    asl_row_kernel<<<B, 256>>>(X, Y, cat, inm, C, B, (float*)d_out);
}